// round 15
// baseline (speedup 1.0000x reference)
#include <cuda_runtime.h>
#include <cuda_fp16.h>

#define SEQ     256
#define VOC     96
#define DEND    (SEQ * VOC)          // 24576 dendrites
#define BATCH   2048
#define SLICES  16
#define PSLICE  (SEQ / SLICES)       // 16 positions per slice
#define SROWS   97                   // 96 char rows + 1 masked row
#define PS_B    (SROWS * VOC)        // 9312 B per position in smem
#define SLICE_B (PSLICE * PS_B)      // 148992 B
#define SMEM_B  (SLICE_B + 128)      // + pad for lanes 24..31 overread
#define GRP_S   256                  // samples per block

// log_w = log(2*sigmoid(x)), x in (-1,1): range [QLO, QLO+1], width exactly 1.
#define QLO   (-0.62011451f)
#define QS7   (1.0f / 127.0f)
#define EPSZ  0.00193274f            // 79/127 + QLO (masked code-79 residual)

// 7-bit unsigned quantized transposed table (96B rows): g_q[d*96+v]
__device__ __align__(128) unsigned char g_q[DEND * VOC + 128];
// u16 partials: scratch[slice][sample][vocab], and per-slice active counts
__device__ unsigned short g_part[SLICES * BATCH * VOC];
__device__ unsigned short g_cnt[SLICES * BATCH];

// ---------------------------------------------------------------------------
// Kernel A: sigmoid/log + 7-bit quantize + transpose. grid (768,3), block (32,8).
// ---------------------------------------------------------------------------
__global__ void prep_kernel(const float* __restrict__ raw) {
    __shared__ float tile[32][33];      // tile[v_local][d_local]
    const int d0 = blockIdx.x * 32;
    const int v0 = blockIdx.y * 32;
    const int tx = threadIdx.x, ty = threadIdx.y;

    #pragma unroll
    for (int i = ty; i < 32; i += 8) {
        const float x = raw[(v0 + i) * DEND + (d0 + tx)];
        tile[i][tx] = 0.69314718f - __logf(1.0f + __expf(-x));
    }
    __syncthreads();

    const int t  = ty * 32 + tx;        // 0..255
    const int dl = t >> 3;              // d_local 0..31
    const int vq = t & 7;               // which uchar4 of 32 v's

    uchar4 c;
    #pragma unroll
    for (int k = 0; k < 4; k++) {
        const float lw = tile[4 * vq + k][dl];
        int qi = __float2int_rn((lw - QLO) * 127.0f);
        qi = max(0, min(127, qi));
        ((unsigned char*)&c)[k] = (unsigned char)qi;
    }
    *(uchar4*)(g_q + (d0 + dl) * VOC + v0 + 4 * vq) = c;
}

// ---------------------------------------------------------------------------
// Kernel B: slice-resident gather. 128 blocks = 16 slices x 8 sample groups,
// 1024 threads, ~146 KB smem (whole table slice). Gathers run at LDS
// latency/bandwidth instead of L2 -> removes the stall floor of R2-R14.
// ---------------------------------------------------------------------------
__global__ void __launch_bounds__(1024, 1)
slice_kernel(const int* __restrict__ chars) {
    extern __shared__ __align__(16) unsigned char sl[];

    const int sliceId = blockIdx.x & (SLICES - 1);
    const int grp     = blockIdx.x >> 4;
    const int P0      = sliceId * PSLICE;
    const int t       = threadIdx.x;              // 0..1023
    const int lane    = t & 31;
    const int w       = t >> 5;                   // 0..31

    // Stage slice: 1536 contiguous 96B rows from g_q -> per-position layout.
    {
        const uint4* __restrict__ src =
            (const uint4*)(g_q + sliceId * (PSLICE * VOC * VOC));
        #pragma unroll
        for (int r = 0; r < 9; r++) {
            const int i   = t + r * 1024;         // 0..9215 uint4
            const int pos = i / 576;              // 576 uint4 per position
            const int rem = i - pos * 576;
            *(uint4*)(sl + pos * PS_B + rem * 16) = src[i];
        }
        // masked row (index 96) per position: bytes = code 79
        if (t < PSLICE * 24) {
            const int pos = t / 24;
            const int wd  = t - pos * 24;
            *(unsigned*)(sl + pos * PS_B + VOC * VOC + wd * 4) = 0x4F4F4F4Fu;
        }
    }
    __syncthreads();

    // 32 warps x 8 samples each = 256 samples for this group.
    #pragma unroll 1
    for (int k = 0; k < GRP_S / 32; k++) {
        const int b = grp * GRP_S + w * (GRP_S / 32) + k;

        // lanes 0..15 hold this sample's chars for positions P0+lane
        int c = 0;
        if (lane < PSLICE) c = chars[b * SEQ + P0 + lane];
        const unsigned am = __ballot_sync(0xffffffffu, (lane < PSLICE) && (c > 0));
        const int cnt = __popc(am);
        // per-lane smem row offset (lane = position within slice)
        const int off = lane * PS_B + ((c > 0) ? (c - 1) : VOC) * VOC;

        unsigned a0 = 0u, a1 = 0u, a2 = 0u, a3 = 0u;
        const int l4 = lane * 4;
        #pragma unroll
        for (int j = 0; j < PSLICE / 2; j++) {
            const int o0 = __shfl_sync(0xffffffffu, off, 2 * j);
            const int o1 = __shfl_sync(0xffffffffu, off, 2 * j + 1);
            const unsigned xa = *(const unsigned*)(sl + o0 + l4);
            const unsigned xb = *(const unsigned*)(sl + o1 + l4);
            const unsigned y  = xa + xb;          // carry-free: bytes <= 254
            a0 = __dp4a(y, 0x00000001u, a0);
            a1 = __dp4a(y, 0x00000100u, a1);
            a2 = __dp4a(y, 0x00010000u, a2);
            a3 = __dp4a(y, 0x01000000u, a3);
        }

        if (lane < 24) {                          // sums <= 2032 -> u16 pack
            const unsigned p0 = a0 | (a1 << 16);
            const unsigned p1 = a2 | (a3 << 16);
            *(uint2*)((unsigned char*)g_part +
                      (size_t)(sliceId * BATCH + b) * (VOC * 2) + lane * 8) =
                make_uint2(p0, p1);
        }
        if (lane == 0) g_cnt[sliceId * BATCH + b] = (unsigned short)cnt;
    }
}

// ---------------------------------------------------------------------------
// Kernel C: reduce 16 slice-partials per sample, exp, store. grid=batch, 96 thr.
// ---------------------------------------------------------------------------
__global__ void reduce_kernel(float* __restrict__ out) {
    const int b = blockIdx.x;
    const int v = threadIdx.x;                    // 0..95

    unsigned s = 0;
    int nact = 0;
    #pragma unroll
    for (int sl = 0; sl < SLICES; sl++) {
        s    += g_part[(sl * BATCH + b) * VOC + v];
        nact += g_cnt[sl * BATCH + b];
    }
    const float inv  = __frcp_rn((float)max(nact, 1));
    const float corr = 256.0f * QLO - (float)(SEQ - nact) * EPSZ;
    out[b * VOC + v] = __expf((QS7 * (float)s + corr) * inv);
}

// ---------------------------------------------------------------------------
extern "C" void kernel_launch(void* const* d_in, const int* in_sizes, int n_in,
                              void* d_out, int out_size) {
    const int*   chars = (const int*)d_in[0];     // (B, 256) int32
    const float* raw   = (const float*)d_in[1];   // (96, 24576) float32
    float*       out   = (float*)d_out;           // (B, 96) float32

    const int batch = in_sizes[0] / SEQ;          // 2048

    static int smem_set = 0;
    if (!smem_set) {                              // idempotent host attr call
        cudaFuncSetAttribute(slice_kernel,
                             cudaFuncAttributeMaxDynamicSharedMemorySize,
                             SMEM_B);
        smem_set = 1;
    }

    dim3 pgrid(DEND / 32, VOC / 32);              // (768, 3)
    dim3 pblk(32, 8);
    prep_kernel<<<pgrid, pblk>>>(raw);

    const int groups = batch / GRP_S;             // 8
    slice_kernel<<<SLICES * groups, 1024, SMEM_B>>>(chars);

    reduce_kernel<<<batch, VOC>>>(out);
}